// round 11
// baseline (speedup 1.0000x reference)
#include <cuda_runtime.h>
#include <cuda_bf16.h>
#include <cstdint>

// Problem constants
#define T_TOTAL 512
#define T_STEPS 511     // reference output uses H[-2] = h after step index 510
#define B_SZ    64
#define D_IN    256
#define HID     1024
#define OUT_SZ  256
#define GROUP_CTAS 64   // CTAs per bb exchange group (jb = 64)
#define ROUNDS   512    // 1 init + 511 steps -> arrivals per CTA per launch

// Scratch (static __device__ — no allocations allowed)
__device__ float g_P[(size_t)T_STEPS * HID * B_SZ];   // [t][j][b]  ~134 MB
__device__ float g_h[2][HID * B_SZ];                  // [j][b] double buffer

// one counting-barrier line per bb group (zero-init; monotone: each launch
// adds exactly GROUP_CTAS*ROUNDS = 64*512; base = floor(cnt/32768)*32768 is
// launch-invariant: before a CTA arrives round 1 the counter can be at most
// base + 63, so every CTA recovers the same base).
__device__ __align__(128) unsigned long long g_cnt[4 * 16];

// ---------------- f32x2 packed-FMA helpers (sm_103a FFMA2) ----------------
__device__ __forceinline__ unsigned long long pack2(float a, float b) {
    unsigned long long r;
    asm("mov.b64 %0, {%1, %2};" : "=l"(r) : "f"(a), "f"(b));
    return r;
}
__device__ __forceinline__ float2 unpack2(unsigned long long v) {
    float2 r;
    asm("mov.b64 {%0, %1}, %2;" : "=f"(r.x), "=f"(r.y) : "l"(v));
    return r;
}
__device__ __forceinline__ void ffma2(unsigned long long& acc,
                                      unsigned long long a,
                                      unsigned long long b) {
    asm("fma.rn.f32x2 %0, %1, %2, %0;" : "+l"(acc) : "l"(a), "l"(b));
}
// L1-bypassing vector load (cross-SM coherent at L2) for the h ring buffer
__device__ __forceinline__ float4 ldcg4(const float4* p) {
    float4 v;
    asm volatile("ld.global.cg.v4.f32 {%0,%1,%2,%3}, [%4];"
                 : "=f"(v.x), "=f"(v.y), "=f"(v.z), "=f"(v.w) : "l"(p));
    return v;
}
__device__ __forceinline__ unsigned long long ld_acquire(const unsigned long long* p) {
    unsigned long long v;
    asm volatile("ld.acquire.gpu.global.u64 %0, [%1];" : "=l"(v) : "l"(p) : "memory");
    return v;
}
__device__ __forceinline__ void red_add_release(unsigned long long* p,
                                                unsigned long long v) {
    asm volatile("red.release.gpu.global.add.u64 [%0], %1;"
                 :: "l"(p), "l"(v) : "memory");
}

// ---------------- precompute: P[t][j][b] = sum_d x[t][b][d]*Wx[d][j] + bias[j] --------
// r4/r8 inner loop (best measured: ~510us). minBlocks=4 forces regs<=64.
__global__ __launch_bounds__(256, 4) void precompute_kernel(
    const float* __restrict__ x, const float* __restrict__ Wx,
    const float* __restrict__ bias)
{
    __shared__ float xs0[64 * 68];  // [b][d]  stride 68
    __shared__ float ws[64 * 64];   // [d][j]

    const int t  = blockIdx.y;
    const int jb = blockIdx.x;
    const int tid = threadIdx.x;
    const int jt = tid & 15;
    const int bt = tid >> 4;

    const float4* x4  = (const float4*)x;
    const float4* Wx4 = (const float4*)Wx;

    unsigned long long acc[4][2];
#pragma unroll
    for (int jj = 0; jj < 4; jj++) { acc[jj][0] = 0ull; acc[jj][1] = 0ull; }

    for (int dt = 0; dt < 4; dt++) {
#pragma unroll
        for (int i = 0; i < 4; i++) {
            int idx = tid + i * 256;
            int b = idx >> 4, q = idx & 15;
            float4 v = x4[(size_t)t * 4096 + b * 64 + dt * 16 + q];
            *(float4*)&xs0[b * 68 + q * 4] = v;
        }
#pragma unroll
        for (int i = 0; i < 4; i++) {
            int idx = tid + i * 256;
            int row = idx >> 4, q = idx & 15;
            *(float4*)&ws[row * 64 + q * 4] =
                Wx4[(size_t)(dt * 64 + row) * 256 + jb * 16 + q];
        }
        __syncthreads();

        const float* xr = &xs0[bt * 4 * 68];
#pragma unroll 8
        for (int dd = 0; dd < 64; dd++) {
            unsigned long long xv0 = pack2(xr[dd], xr[dd + 68]);
            unsigned long long xv1 = pack2(xr[dd + 136], xr[dd + 204]);
            float4 wv = *(const float4*)&ws[dd * 64 + jt * 4];
            unsigned long long w0 = pack2(wv.x, wv.x);
            unsigned long long w1 = pack2(wv.y, wv.y);
            unsigned long long w2 = pack2(wv.z, wv.z);
            unsigned long long w3 = pack2(wv.w, wv.w);
            ffma2(acc[0][0], xv0, w0); ffma2(acc[0][1], xv1, w0);
            ffma2(acc[1][0], xv0, w1); ffma2(acc[1][1], xv1, w1);
            ffma2(acc[2][0], xv0, w2); ffma2(acc[2][1], xv1, w2);
            ffma2(acc[3][0], xv0, w3); ffma2(acc[3][1], xv1, w3);
        }
        __syncthreads();
    }

    const int b0 = bt * 4;
#pragma unroll
    for (int jj = 0; jj < 4; jj++) {
        int j = jb * 64 + jt * 4 + jj;
        float bj = bias[j];
        float2 a0 = unpack2(acc[jj][0]);
        float2 a1 = unpack2(acc[jj][1]);
        float4 o = make_float4(a0.x + bj, a0.y + bj, a1.x + bj, a1.y + bj);
        *(float4*)&g_P[((size_t)t * HID + j) * B_SZ + b0] = o;
    }
}

// ---------------- persistent recurrence kernel (v9: 2 chains per SM) ----------------
// grid (64 jb, 4 bb) = 256 CTAs of 256 threads; 96 KB smem/CTA -> 2 CTAs/SM,
// all resident in one wave (capacity 296). Co-resident pairs are ALWAYS from
// different bb chains (bid & bid+148 differ by >=2 in bb), so one chain's
// compute fills the other chain's barrier/exchange gaps.
// Per CTA: j-tile 16 (Wh slice 64 KB in smem), 8 warps, warp k-slice 128,
// lane tile 2j x 4b (4 f32x2 accs). h staged in 4 ping-pong 32k chunks.
// Sync: counting barrier per bb group (64 arrivals/round), red.add.release
// arrive, tid0 polls with nanosleep.
__global__ __launch_bounds__(256, 2) void rnn_persistent_kernel(const float* __restrict__ Wh)
{
    extern __shared__ float smem[];
    float* whs    = smem;            // [1024 k][16 j]          = 16384 floats (64 KB)
    float* hstage = smem + 16384;    // [8 warp][2 buf][512]    =  8192 floats (32 KB)
                                     // (warp region 1024 f; first 256 reused
                                     //  as reduction partials)

    const int tid = threadIdx.x;
    const int w   = tid >> 5;          // 8 warps
    const int l   = tid & 31;
    const int jp  = l & 7;             // j pair: j_local = jp*2 + {0,1}   (16 j)
    const int bq  = l >> 3;            // b quarter: b_local = bq*4 + {0..3} (16 b)
    const int jb  = blockIdx.x;        // 64 blocks of 16 j
    const int bb  = blockIdx.y;        // 4 blocks of 16 b

    unsigned long long* const cnt = &g_cnt[bb * 16];
    const unsigned long long per_launch =
        (unsigned long long)GROUP_CTAS * (unsigned long long)ROUNDS;   // 32768
    const unsigned long long base = (*cnt / per_launch) * per_launch;

    // ---- load Wh slice into smem once: whs[k*16 + jl] ----
    {
        const float4* wh4  = (const float4*)Wh;    // Wh[k][j], row = 256 f4
        float4*       whs4 = (float4*)whs;         // row = 4 f4
#pragma unroll
        for (int i = 0; i < 16; i++) {
            int idx = tid + i * 256;               // 4096 float4
            int k = idx >> 2, q = idx & 3;
            whs4[k * 4 + q] = wh4[(size_t)k * 256 + jb * 4 + q];
        }
    }
    // ---- zero h0 slice (16j x 16b), arrive round 1 ----
    {
        int jl = tid >> 4, bl = tid & 15;
        g_h[0][(jb * 16 + jl) * B_SZ + bb * 16 + bl] = 0.f;
    }
    __syncthreads();
    if (tid == 0) red_add_release(cnt, 1ULL);

    const int k0w = w * 128;           // warp's k slice [k0w, k0w+128)
    float* hst = hstage + w * 1024;    // 2 buffers x 512 floats

    const float* pptr0 = &g_P[((size_t)(jb * 16 + (tid >> 4))) * B_SZ + bb * 16 + (tid & 15)];
    float* const hn_base0 = &g_h[0][(jb * 16 + (tid >> 4)) * B_SZ + bb * 16 + (tid & 15)];
    float* const hn_base1 = &g_h[1][(jb * 16 + (tid >> 4)) * B_SZ + bb * 16 + (tid & 15)];

    // per-lane chunk staging index math: 32k x 16b chunk = 128 f4, 4 per lane
    const int c_kk[4] = { (l) >> 2, (l + 32) >> 2, (l + 64) >> 2, (l + 96) >> 2 };
    const int c_q[4]  = { (l) & 3,  (l + 32) & 3,  (l + 64) & 3,  (l + 96) & 3  };

    // P double-buffer: load P[0] up front (hidden under the round-1 wait)
    float pval = __ldcs(pptr0);

    for (int t = 0; t < T_STEPS; t++) {
        const float4* hp4 = (const float4*)g_h[t & 1];   // h[k][b], row = 16 f4

        // P[t+1] prefetch BEFORE the wait (barrier-independent; drains under poll)
        float pnext = 0.f;
        if (t + 1 < T_STEPS)
            pnext = __ldcs(pptr0 + (size_t)(t + 1) * (HID * B_SZ));

        // ---- wait for round t+1 (everyone in this chain published h_t) ----
        if (tid == 0) {
            const unsigned long long need =
                base + (unsigned long long)GROUP_CTAS * (unsigned long long)(t + 1);
            while (ld_acquire(cnt) < need) { __nanosleep(64); }
        }
        __syncthreads();

        unsigned long long acc[2][2];
        acc[0][0] = acc[0][1] = acc[1][0] = acc[1][1] = 0ull;

        const float* wrow = whs + (size_t)k0w * 16;

        // ---- 4 ping-pong chunks of 32k ----
        float4 hreg[4];
        // prefetch chunk 0
#pragma unroll
        for (int i = 0; i < 4; i++)
            hreg[i] = ldcg4(&hp4[(size_t)(k0w + c_kk[i]) * 16 + bb * 4 + c_q[i]]);

#pragma unroll
        for (int c = 0; c < 4; c++) {
            const int buf = c & 1;
            // stage prefetched chunk
#pragma unroll
            for (int i = 0; i < 4; i++)
                *(float4*)&hst[buf * 512 + c_kk[i] * 16 + c_q[i] * 4] = hreg[i];
            __syncwarp();
            // prefetch next chunk (drains under compute below)
            if (c < 3) {
                const int k0 = k0w + (c + 1) * 32;
#pragma unroll
                for (int i = 0; i < 4; i++)
                    hreg[i] = ldcg4(&hp4[(size_t)(k0 + c_kk[i]) * 16 + bb * 4 + c_q[i]]);
            }
            // compute 32 k from smem: per k, 1 LDS.128 + 1 LDS.64 + 2 pack + 4 FFMA2
            const float* wc = wrow + (size_t)c * 32 * 16;
#pragma unroll
            for (int kk = 0; kk < 32; kk++) {
                ulonglong2 hv = *(const ulonglong2*)&hst[buf * 512 + kk * 16 + bq * 4];
                float2 wp = *(const float2*)&wc[kk * 16 + jp * 2];
                unsigned long long w0 = pack2(wp.x, wp.x);
                unsigned long long w1 = pack2(wp.y, wp.y);
                ffma2(acc[0][0], hv.x, w0);
                ffma2(acc[0][1], hv.y, w0);
                ffma2(acc[1][0], hv.x, w1);
                ffma2(acc[1][1], hv.y, w1);
            }
            __syncwarp();
        }

        // write k-partials into own warp region (first 256 floats)
#pragma unroll
        for (int jj = 0; jj < 2; jj++) {
            int o = (jp * 2 + jj) * 16 + bq * 4;
            float2 a0 = unpack2(acc[jj][0]), a1 = unpack2(acc[jj][1]);
            *(float4*)&hst[o] = make_float4(a0.x, a0.y, a1.x, a1.y);
        }
        __syncthreads();

        // each thread finalizes one output o = tid (jl = o>>4, bl = o&15)
        {
            float s = 0.f;
#pragma unroll
            for (int ww = 0; ww < 8; ww++) s += hstage[ww * 1024 + tid];
            float* hn = ((t + 1) & 1) ? hn_base1 : hn_base0;
            *hn = tanhf(pval + s);
        }
        __syncthreads();
        if (tid == 0) red_add_release(cnt, 1ULL);   // arrive round t+2

        pval = pnext;
    }
}

// ---------------- final: y[b][o] = sum_j h[j][b]*W2[j][o] + b2[o] ----------------
__global__ __launch_bounds__(128) void final_kernel(
    const float* __restrict__ W2, const float* __restrict__ b2,
    float* __restrict__ out)
{
    __shared__ float hs[128 * 16];
    __shared__ float ws[128 * 32];

    const int tid = threadIdx.x;
    const int ol = tid & 31;
    const int bt = tid >> 5;
    const int ob = blockIdx.x;
    const int bb = blockIdx.y;

    const float* hfin = g_h[T_STEPS & 1];
    const float4* hp4 = (const float4*)hfin;
    const float4* w24 = (const float4*)W2;

    unsigned long long acc0 = 0ull, acc1 = 0ull;

    for (int c = 0; c < 8; c++) {
        const int k0 = c * 128;
#pragma unroll
        for (int i = 0; i < 4; i++) {
            int idx = tid + i * 128; int row = idx >> 2, q = idx & 3;
            *(float4*)&hs[row * 16 + q * 4] = hp4[(size_t)(k0 + row) * 16 + bb * 4 + q];
        }
#pragma unroll
        for (int i = 0; i < 8; i++) {
            int idx = tid + i * 128; int row = idx >> 3, q = idx & 7;
            *(float4*)&ws[row * 32 + q * 4] = w24[(size_t)(k0 + row) * 64 + ob * 8 + q];
        }
        __syncthreads();
#pragma unroll 8
        for (int kk = 0; kk < 128; kk++) {
            ulonglong2 hv = *(const ulonglong2*)&hs[kk * 16 + bt * 4];
            float w = ws[kk * 32 + ol];
            unsigned long long wp = pack2(w, w);
            ffma2(acc0, hv.x, wp);
            ffma2(acc1, hv.y, wp);
        }
        __syncthreads();
    }

    const int o = ob * 32 + ol;
    const int b0 = bb * 16 + bt * 4;
    const float bo = b2[o];
    float2 a0 = unpack2(acc0), a1 = unpack2(acc1);
    out[(b0 + 0) * OUT_SZ + o] = a0.x + bo;
    out[(b0 + 1) * OUT_SZ + o] = a0.y + bo;
    out[(b0 + 2) * OUT_SZ + o] = a1.x + bo;
    out[(b0 + 3) * OUT_SZ + o] = a1.y + bo;
}

// ---------------- launch ----------------
extern "C" void kernel_launch(void* const* d_in, const int* in_sizes, int n_in,
                              void* d_out, int out_size)
{
    const float* x   = (const float*)d_in[0];
    const float* Wx  = (const float*)d_in[1];
    const float* Wh  = (const float*)d_in[2];
    const float* b   = (const float*)d_in[3];
    const float* W2  = (const float*)d_in[4];
    const float* b2  = (const float*)d_in[5];
    float* out = (float*)d_out;

    const int SMEM_BYTES = (16384 + 8192) * 4;   // 96 KB dynamic smem
    static bool attr_done = false;
    if (!attr_done) {
        cudaFuncSetAttribute(rnn_persistent_kernel,
                             cudaFuncAttributeMaxDynamicSharedMemorySize, SMEM_BYTES);
        attr_done = true;
    }

    precompute_kernel<<<dim3(16, T_STEPS), 256>>>(x, Wx, b);
    rnn_persistent_kernel<<<dim3(64, 4), 256, SMEM_BYTES>>>(Wh);
    final_kernel<<<dim3(8, 4), 128>>>(W2, b2, out);
}

// round 12
// speedup vs baseline: 1.2857x; 1.2857x over previous
#include <cuda_runtime.h>
#include <cuda_bf16.h>
#include <cstdint>

// Problem constants
#define T_TOTAL 512
#define T_STEPS 511     // reference output uses H[-2] = h after step index 510
#define B_SZ    64
#define D_IN    256
#define HID     1024
#define OUT_SZ  256
#define GROUP_CTAS 32   // CTAs per bb exchange group
#define ROUNDS   512    // 1 init + 511 steps

// Scratch (static __device__ — no allocations allowed)
__device__ float g_P[(size_t)T_STEPS * HID * B_SZ];   // [t][j][b]  ~134 MB
__device__ float g_h[2][HID * B_SZ];                  // [j][b] double buffer

// barrier counters (one line per bb group) + per-(t,jb) P-ready flags.
// BOTH are zeroed by reset_kernel at the start of every launch, so all
// thresholds are absolute (no monotone-base recovery needed).
__device__ __align__(128) unsigned long long g_cnt[4 * 16];
__device__ unsigned long long g_pflag[(size_t)T_STEPS * 16];   // [t][jb_pre]

// ---------------- f32x2 packed-FMA helpers (sm_103a FFMA2) ----------------
__device__ __forceinline__ unsigned long long pack2(float a, float b) {
    unsigned long long r;
    asm("mov.b64 %0, {%1, %2};" : "=l"(r) : "f"(a), "f"(b));
    return r;
}
__device__ __forceinline__ float2 unpack2(unsigned long long v) {
    float2 r;
    asm("mov.b64 {%0, %1}, %2;" : "=f"(r.x), "=f"(r.y) : "l"(v));
    return r;
}
__device__ __forceinline__ void ffma2(unsigned long long& acc,
                                      unsigned long long a,
                                      unsigned long long b) {
    asm("fma.rn.f32x2 %0, %1, %2, %0;" : "+l"(acc) : "l"(a), "l"(b));
}
__device__ __forceinline__ float4 ldcg4(const float4* p) {
    float4 v;
    asm volatile("ld.global.cg.v4.f32 {%0,%1,%2,%3}, [%4];"
                 : "=f"(v.x), "=f"(v.y), "=f"(v.z), "=f"(v.w) : "l"(p));
    return v;
}
__device__ __forceinline__ unsigned long long ld_acquire(const unsigned long long* p) {
    unsigned long long v;
    asm volatile("ld.acquire.gpu.global.u64 %0, [%1];" : "=l"(v) : "l"(p) : "memory");
    return v;
}
__device__ __forceinline__ void st_release(unsigned long long* p, unsigned long long v) {
    asm volatile("st.release.gpu.global.u64 [%0], %1;" :: "l"(p), "l"(v) : "memory");
}
__device__ __forceinline__ void red_add_release(unsigned long long* p,
                                                unsigned long long v) {
    asm volatile("red.release.gpu.global.add.u64 [%0], %1;"
                 :: "l"(p), "l"(v) : "memory");
}

// ---------------- reset: zero barrier counters + P-ready flags ----------------
__global__ void reset_kernel() {
    int idx = blockIdx.x * blockDim.x + threadIdx.x;
    if (idx < 4 * 16) g_cnt[idx] = 0ULL;
    for (int i = idx; i < T_STEPS * 16; i += gridDim.x * blockDim.x)
        g_pflag[i] = 0ULL;
}

// ---------------- precompute: P[t][j][b] = sum_d x[t][b][d]*Wx[d][j] + bias[j] --------
// r8 inner loop (best measured ~510us standalone). Sets g_pflag[t][jb] when
// its slice is fully stored (release after syncthreads).
__global__ __launch_bounds__(256, 4) void precompute_kernel(
    const float* __restrict__ x, const float* __restrict__ Wx,
    const float* __restrict__ bias)
{
    __shared__ float xs0[64 * 68];  // [b][d]  stride 68
    __shared__ float ws[64 * 64];   // [d][j]

    const int t  = blockIdx.y;
    const int jb = blockIdx.x;
    const int tid = threadIdx.x;
    const int jt = tid & 15;
    const int bt = tid >> 4;

    const float4* x4  = (const float4*)x;
    const float4* Wx4 = (const float4*)Wx;

    unsigned long long acc[4][2];
#pragma unroll
    for (int jj = 0; jj < 4; jj++) { acc[jj][0] = 0ull; acc[jj][1] = 0ull; }

    for (int dt = 0; dt < 4; dt++) {
#pragma unroll
        for (int i = 0; i < 4; i++) {
            int idx = tid + i * 256;
            int b = idx >> 4, q = idx & 15;
            float4 v = x4[(size_t)t * 4096 + b * 64 + dt * 16 + q];
            *(float4*)&xs0[b * 68 + q * 4] = v;
        }
#pragma unroll
        for (int i = 0; i < 4; i++) {
            int idx = tid + i * 256;
            int row = idx >> 4, q = idx & 15;
            *(float4*)&ws[row * 64 + q * 4] =
                Wx4[(size_t)(dt * 64 + row) * 256 + jb * 16 + q];
        }
        __syncthreads();

        const float* xr = &xs0[bt * 4 * 68];
#pragma unroll 8
        for (int dd = 0; dd < 64; dd++) {
            unsigned long long xv0 = pack2(xr[dd], xr[dd + 68]);
            unsigned long long xv1 = pack2(xr[dd + 136], xr[dd + 204]);
            float4 wv = *(const float4*)&ws[dd * 64 + jt * 4];
            unsigned long long w0 = pack2(wv.x, wv.x);
            unsigned long long w1 = pack2(wv.y, wv.y);
            unsigned long long w2 = pack2(wv.z, wv.z);
            unsigned long long w3 = pack2(wv.w, wv.w);
            ffma2(acc[0][0], xv0, w0); ffma2(acc[0][1], xv1, w0);
            ffma2(acc[1][0], xv0, w1); ffma2(acc[1][1], xv1, w1);
            ffma2(acc[2][0], xv0, w2); ffma2(acc[2][1], xv1, w2);
            ffma2(acc[3][0], xv0, w3); ffma2(acc[3][1], xv1, w3);
        }
        __syncthreads();
    }

    const int b0 = bt * 4;
#pragma unroll
    for (int jj = 0; jj < 4; jj++) {
        int j = jb * 64 + jt * 4 + jj;
        float bj = bias[j];
        float2 a0 = unpack2(acc[jj][0]);
        float2 a1 = unpack2(acc[jj][1]);
        float4 o = make_float4(a0.x + bj, a0.y + bj, a1.x + bj, a1.y + bj);
        *(float4*)&g_P[((size_t)t * HID + j) * B_SZ + b0] = o;
    }

    // publish slice readiness (syncthreads orders all threads' stores before
    // tid0's release — same pattern as the h-exchange barrier)
    __syncthreads();
    if (tid == 0) st_release(&g_pflag[(size_t)t * 16 + jb], 1ULL);
}

// ---------------- persistent recurrence kernel (r8 + P-flag gating) ----------
// grid (32 jb, 4 bb) = 128 CTAs, 512 threads = 16 warps. All CTAs resident.
// Wh slice [1024 k][32 j] in smem (128 KB). Counting barrier per bb group.
// P[t] readiness gated by g_pflag[t][jb>>1] (produced concurrently).
__global__ __launch_bounds__(512) void rnn_persistent_kernel(const float* __restrict__ Wh)
{
    extern __shared__ float smem[];
    float* whs    = smem;            // [1024 k][32 j]        = 32768 floats (128 KB)
    float* hstage = smem + 32768;    // [16 warp][1024]       = 16384 floats (64 KB)

    const int tid = threadIdx.x;
    const int w   = tid >> 5;
    const int l   = tid & 31;
    const int jp  = l & 15;            // j pair: j_local = jp*2 + {0,1}
    const int bh  = l >> 4;            // b half: b_local = bh*8 + {0..7}
    const int jb  = blockIdx.x;        // 32 blocks of 32 j
    const int bb  = blockIdx.y;        // 4 blocks of 16 b

    unsigned long long* const cnt = &g_cnt[bb * 16];
    const unsigned long long* const pflag_base = &g_pflag[jb >> 1];

    // ---- load Wh slice into smem once: whs[k*32 + jl] ----
    {
        const float4* wh4  = (const float4*)Wh;    // Wh[k][j], row = 256 f4
        float4*       whs4 = (float4*)whs;         // row = 8 f4
#pragma unroll
        for (int i = 0; i < 16; i++) {
            int idx = tid + i * 512;               // 8192 float4
            int k = idx >> 3, q = idx & 7;
            whs4[k * 8 + q] = wh4[(size_t)k * 256 + jb * 8 + q];
        }
    }
    // ---- zero h0 slice, arrive round 1 ----
    {
        int jl = tid >> 4, bl = tid & 15;
        g_h[0][(jb * 32 + jl) * B_SZ + bb * 16 + bl] = 0.f;
    }
    __syncthreads();
    if (tid == 0) red_add_release(cnt, 1ULL);

    const int k0w = w * 64;
    float* hst = hstage + w * 1024;

    const float* pptr0 = &g_P[((size_t)(jb * 32 + (tid >> 4))) * B_SZ + bb * 16 + (tid & 15)];
    float* const hn_base0 = &g_h[0][(jb * 32 + (tid >> 4)) * B_SZ + bb * 16 + (tid & 15)];
    float* const hn_base1 = &g_h[1][(jb * 32 + (tid >> 4)) * B_SZ + bb * 16 + (tid & 15)];

    // per-lane chunk staging index math: 32k x 16b chunk = 128 f4, 4 per lane
    const int c_kk[4] = { (l) >> 2, (l + 32) >> 2, (l + 64) >> 2, (l + 96) >> 2 };
    const int c_q[4]  = { (l) & 3,  (l + 32) & 3,  (l + 64) & 3,  (l + 96) & 3  };

    for (int t = 0; t < T_STEPS; t++) {
        const float4* hp4 = (const float4*)g_h[t & 1];   // h[k][b], row = 16 f4

        // ---- wait: all CTAs published h_t AND P[t] slice is produced ----
        if (tid == 0) {
            const unsigned long long need =
                (unsigned long long)GROUP_CTAS * (unsigned long long)(t + 1);
            while (ld_acquire(cnt) < need) { __nanosleep(64); }
            const unsigned long long* pf = pflag_base + (size_t)t * 16;
            while (ld_acquire(pf) == 0ULL) { __nanosleep(64); }
        }
        __syncthreads();

        // P[t] load issued now; consumed ~4K cycles later at the epilogue
        float pval = __ldcs(pptr0 + (size_t)t * (HID * B_SZ));

        // ---- chunk A load (k0w .. k0w+32) ----
        float4 ha[4];
#pragma unroll
        for (int i = 0; i < 4; i++)
            ha[i] = ldcg4(&hp4[(size_t)(k0w + c_kk[i]) * 16 + bb * 4 + c_q[i]]);
#pragma unroll
        for (int i = 0; i < 4; i++)
            *(float4*)&hst[c_kk[i] * 16 + c_q[i] * 4] = ha[i];
        __syncwarp();

        // ---- chunk B load issued (k0w+32 .. k0w+64), drains under compute A ----
        float4 hb[4];
#pragma unroll
        for (int i = 0; i < 4; i++)
            hb[i] = ldcg4(&hp4[(size_t)(k0w + 32 + c_kk[i]) * 16 + bb * 4 + c_q[i]]);

        unsigned long long acc[2][4];
#pragma unroll
        for (int jj = 0; jj < 2; jj++)
#pragma unroll
            for (int p = 0; p < 4; p++) acc[jj][p] = 0ull;

        const float* wrow = whs + (size_t)k0w * 32;

        // ---- compute chunk A ----
#pragma unroll
        for (int kk = 0; kk < 32; kk++) {
            ulonglong2 hv01 = *(const ulonglong2*)&hst[kk * 16 + bh * 8];
            ulonglong2 hv23 = *(const ulonglong2*)&hst[kk * 16 + bh * 8 + 4];
            float2 wp = *(const float2*)&wrow[kk * 32 + jp * 2];
            unsigned long long w0 = pack2(wp.x, wp.x);
            unsigned long long w1 = pack2(wp.y, wp.y);
            ffma2(acc[0][0], hv01.x, w0);
            ffma2(acc[0][1], hv01.y, w0);
            ffma2(acc[0][2], hv23.x, w0);
            ffma2(acc[0][3], hv23.y, w0);
            ffma2(acc[1][0], hv01.x, w1);
            ffma2(acc[1][1], hv01.y, w1);
            ffma2(acc[1][2], hv23.x, w1);
            ffma2(acc[1][3], hv23.y, w1);
        }

        // ---- stage chunk B, compute it ----
#pragma unroll
        for (int i = 0; i < 4; i++)
            *(float4*)&hst[(32 + c_kk[i]) * 16 + c_q[i] * 4] = hb[i];
        __syncwarp();

#pragma unroll
        for (int kk = 32; kk < 64; kk++) {
            ulonglong2 hv01 = *(const ulonglong2*)&hst[kk * 16 + bh * 8];
            ulonglong2 hv23 = *(const ulonglong2*)&hst[kk * 16 + bh * 8 + 4];
            float2 wp = *(const float2*)&wrow[kk * 32 + jp * 2];
            unsigned long long w0 = pack2(wp.x, wp.x);
            unsigned long long w1 = pack2(wp.y, wp.y);
            ffma2(acc[0][0], hv01.x, w0);
            ffma2(acc[0][1], hv01.y, w0);
            ffma2(acc[0][2], hv23.x, w0);
            ffma2(acc[0][3], hv23.y, w0);
            ffma2(acc[1][0], hv01.x, w1);
            ffma2(acc[1][1], hv01.y, w1);
            ffma2(acc[1][2], hv23.x, w1);
            ffma2(acc[1][3], hv23.y, w1);
        }

        // write k-partials into own warp region
#pragma unroll
        for (int jj = 0; jj < 2; jj++) {
            int o = (jp * 2 + jj) * 16 + bh * 8;
            float2 a0 = unpack2(acc[jj][0]), a1 = unpack2(acc[jj][1]);
            float2 a2 = unpack2(acc[jj][2]), a3 = unpack2(acc[jj][3]);
            *(float4*)&hst[o]     = make_float4(a0.x, a0.y, a1.x, a1.y);
            *(float4*)&hst[o + 4] = make_float4(a2.x, a2.y, a3.x, a3.y);
        }
        __syncthreads();

        // each thread finalizes one output o = tid, stores h_{t+1}
        {
            float s = 0.f;
#pragma unroll
            for (int ww = 0; ww < 16; ww++) s += hstage[ww * 1024 + tid];
            float* hn = ((t + 1) & 1) ? hn_base1 : hn_base0;
            *hn = tanhf(pval + s);
        }
        __syncthreads();
        if (tid == 0) red_add_release(cnt, 1ULL);   // arrive round t+2
    }
}

// ---------------- final: y[b][o] = sum_j h[j][b]*W2[j][o] + b2[o] ----------------
__global__ __launch_bounds__(128) void final_kernel(
    const float* __restrict__ W2, const float* __restrict__ b2,
    float* __restrict__ out)
{
    __shared__ float hs[128 * 16];
    __shared__ float ws[128 * 32];

    const int tid = threadIdx.x;
    const int ol = tid & 31;
    const int bt = tid >> 5;
    const int ob = blockIdx.x;
    const int bb = blockIdx.y;

    const float* hfin = g_h[T_STEPS & 1];
    const float4* hp4 = (const float4*)hfin;
    const float4* w24 = (const float4*)W2;

    unsigned long long acc0 = 0ull, acc1 = 0ull;

    for (int c = 0; c < 8; c++) {
        const int k0 = c * 128;
#pragma unroll
        for (int i = 0; i < 4; i++) {
            int idx = tid + i * 128; int row = idx >> 2, q = idx & 3;
            *(float4*)&hs[row * 16 + q * 4] = hp4[(size_t)(k0 + row) * 16 + bb * 4 + q];
        }
#pragma unroll
        for (int i = 0; i < 8; i++) {
            int idx = tid + i * 128; int row = idx >> 3, q = idx & 7;
            *(float4*)&ws[row * 32 + q * 4] = w24[(size_t)(k0 + row) * 64 + ob * 8 + q];
        }
        __syncthreads();
#pragma unroll 8
        for (int kk = 0; kk < 128; kk++) {
            ulonglong2 hv = *(const ulonglong2*)&hs[kk * 16 + bt * 4];
            float w = ws[kk * 32 + ol];
            unsigned long long wp = pack2(w, w);
            ffma2(acc0, hv.x, wp);
            ffma2(acc1, hv.y, wp);
        }
        __syncthreads();
    }

    const int o = ob * 32 + ol;
    const int b0 = bb * 16 + bt * 4;
    const float bo = b2[o];
    float2 a0 = unpack2(acc0), a1 = unpack2(acc1);
    out[(b0 + 0) * OUT_SZ + o] = a0.x + bo;
    out[(b0 + 1) * OUT_SZ + o] = a0.y + bo;
    out[(b0 + 2) * OUT_SZ + o] = a1.x + bo;
    out[(b0 + 3) * OUT_SZ + o] = a1.y + bo;
}

// ---------------- launch: reset -> fork(precompute || persistent) -> join -> final ----
extern "C" void kernel_launch(void* const* d_in, const int* in_sizes, int n_in,
                              void* d_out, int out_size)
{
    const float* x   = (const float*)d_in[0];
    const float* Wx  = (const float*)d_in[1];
    const float* Wh  = (const float*)d_in[2];
    const float* b   = (const float*)d_in[3];
    const float* W2  = (const float*)d_in[4];
    const float* b2  = (const float*)d_in[5];
    float* out = (float*)d_out;

    const int SMEM_BYTES = (32768 + 16384) * 4;   // 192 KB dynamic smem

    static bool init_done = false;
    static cudaStream_t s_side;
    static cudaEvent_t ev_fork, ev_join;
    if (!init_done) {
        cudaFuncSetAttribute(rnn_persistent_kernel,
                             cudaFuncAttributeMaxDynamicSharedMemorySize, SMEM_BYTES);
        cudaStreamCreateWithFlags(&s_side, cudaStreamNonBlocking);
        cudaEventCreateWithFlags(&ev_fork, cudaEventDisableTiming);
        cudaEventCreateWithFlags(&ev_join, cudaEventDisableTiming);
        init_done = true;
    }

    // reset counters + flags (both branches depend on this)
    reset_kernel<<<17, 512>>>();

    // fork: precompute on side stream, persistent on main stream
    cudaEventRecord(ev_fork, 0);
    cudaStreamWaitEvent(s_side, ev_fork, 0);
    precompute_kernel<<<dim3(16, T_STEPS), 256, 0, s_side>>>(x, Wx, b);
    cudaEventRecord(ev_join, s_side);

    rnn_persistent_kernel<<<dim3(32, 4), 512, SMEM_BYTES>>>(Wh);

    // join side branch back into main stream, then epilogue
    cudaStreamWaitEvent(0, ev_join, 0);
    final_kernel<<<dim3(8, 4), 128>>>(W2, b2, out);
}

// round 14
// speedup vs baseline: 1.3186x; 1.0256x over previous
#include <cuda_runtime.h>
#include <cuda_bf16.h>
#include <cstdint>

// Problem constants
#define T_TOTAL 512
#define T_STEPS 511     // reference output uses H[-2] = h after step index 510
#define B_SZ    64
#define D_IN    256
#define HID     1024
#define OUT_SZ  256
#define GROUP_CTAS 32   // CTAs per bb exchange group
#define ROUNDS   512    // 1 init + 511 steps -> arrivals per CTA per launch

// Scratch (static __device__ — no allocations allowed)
__device__ float g_P[(size_t)T_STEPS * HID * B_SZ];   // [t][j][b]  ~134 MB
__device__ float g_h[2][HID * B_SZ];                  // [j][b] double buffer

// one counting-barrier line per bb group (zero-init; monotone: each launch
// adds exactly GROUP_CTAS*ROUNDS, so base = floor(cnt / (32*512)) * (32*512)
// is launch-invariant even if CTAs read it at slightly different times).
__device__ __align__(128) unsigned long long g_cnt[4 * 16];

// ---------------- f32x2 packed-FMA helpers (sm_103a FFMA2) ----------------
__device__ __forceinline__ unsigned long long pack2(float a, float b) {
    unsigned long long r;
    asm("mov.b64 %0, {%1, %2};" : "=l"(r) : "f"(a), "f"(b));
    return r;
}
__device__ __forceinline__ float2 unpack2(unsigned long long v) {
    float2 r;
    asm("mov.b64 {%0, %1}, %2;" : "=f"(r.x), "=f"(r.y) : "l"(v));
    return r;
}
__device__ __forceinline__ void ffma2(unsigned long long& acc,
                                      unsigned long long a,
                                      unsigned long long b) {
    asm("fma.rn.f32x2 %0, %1, %2, %0;" : "+l"(acc) : "l"(a), "l"(b));
}
// L1-bypassing vector load (cross-SM coherent at L2) for the h ring buffer
__device__ __forceinline__ float4 ldcg4(const float4* p) {
    float4 v;
    asm volatile("ld.global.cg.v4.f32 {%0,%1,%2,%3}, [%4];"
                 : "=f"(v.x), "=f"(v.y), "=f"(v.z), "=f"(v.w) : "l"(p));
    return v;
}
__device__ __forceinline__ unsigned long long ld_acquire(const unsigned long long* p) {
    unsigned long long v;
    asm volatile("ld.acquire.gpu.global.u64 %0, [%1];" : "=l"(v) : "l"(p) : "memory");
    return v;
}
__device__ __forceinline__ void red_add_release(unsigned long long* p,
                                                unsigned long long v) {
    asm volatile("red.release.gpu.global.add.u64 [%0], %1;"
                 :: "l"(p), "l"(v) : "memory");
}

// ---------------- precompute: P[t][j][b] = sum_d x[t][b][d]*Wx[d][j] + bias[j] --------
// v4b: x staged at ODD row stride 65 (inner-loop x reads: 8-way -> ~2-way
// bank conflicts). ws explicitly 16B-aligned: xs0's size is no longer a
// multiple of 16B, which previously left ws misaligned for float4 access
// (the r13 crash). Staging x uses scalar stores. minBlocks=4 -> regs<=64.
__global__ __launch_bounds__(256, 4) void precompute_kernel(
    const float* __restrict__ x, const float* __restrict__ Wx,
    const float* __restrict__ bias)
{
    __shared__ __align__(16) float xs0[64 * 65 + 4];  // [b][d]  ODD stride 65
    __shared__ __align__(16) float ws[64 * 64];       // [d][j]  float4-accessed

    const int t  = blockIdx.y;
    const int jb = blockIdx.x;
    const int tid = threadIdx.x;
    const int jt = tid & 15;
    const int bt = tid >> 4;

    const float4* x4  = (const float4*)x;
    const float4* Wx4 = (const float4*)Wx;

    unsigned long long acc[4][2];
#pragma unroll
    for (int jj = 0; jj < 4; jj++) { acc[jj][0] = 0ull; acc[jj][1] = 0ull; }

    for (int dt = 0; dt < 4; dt++) {
        // stage x tile: natural [b][d], odd stride, scalar stores
#pragma unroll
        for (int i = 0; i < 4; i++) {
            int idx = tid + i * 256;
            int b = idx >> 4, q = idx & 15;
            float4 v = x4[(size_t)t * 4096 + b * 64 + dt * 16 + q];
            float* dst = &xs0[b * 65 + q * 4];
            dst[0] = v.x; dst[1] = v.y; dst[2] = v.z; dst[3] = v.w;
        }
        // stage Wx tile : ws[d][j] (float4, conflict-free, 16B-aligned)
#pragma unroll
        for (int i = 0; i < 4; i++) {
            int idx = tid + i * 256;
            int row = idx >> 4, q = idx & 15;
            *(float4*)&ws[row * 64 + q * 4] =
                Wx4[(size_t)(dt * 64 + row) * 256 + jb * 16 + q];
        }
        __syncthreads();

        const float* xr = &xs0[bt * 4 * 65];
#pragma unroll 8
        for (int dd = 0; dd < 64; dd++) {
            unsigned long long xv0 = pack2(xr[dd], xr[dd + 65]);
            unsigned long long xv1 = pack2(xr[dd + 130], xr[dd + 195]);
            float4 wv = *(const float4*)&ws[dd * 64 + jt * 4];
            unsigned long long w0 = pack2(wv.x, wv.x);
            unsigned long long w1 = pack2(wv.y, wv.y);
            unsigned long long w2 = pack2(wv.z, wv.z);
            unsigned long long w3 = pack2(wv.w, wv.w);
            ffma2(acc[0][0], xv0, w0); ffma2(acc[0][1], xv1, w0);
            ffma2(acc[1][0], xv0, w1); ffma2(acc[1][1], xv1, w1);
            ffma2(acc[2][0], xv0, w2); ffma2(acc[2][1], xv1, w2);
            ffma2(acc[3][0], xv0, w3); ffma2(acc[3][1], xv1, w3);
        }
        __syncthreads();
    }

    const int b0 = bt * 4;
#pragma unroll
    for (int jj = 0; jj < 4; jj++) {
        int j = jb * 64 + jt * 4 + jj;
        float bj = bias[j];
        float2 a0 = unpack2(acc[jj][0]);
        float2 a1 = unpack2(acc[jj][1]);
        float4 o = make_float4(a0.x + bj, a0.y + bj, a1.x + bj, a1.y + bj);
        *(float4*)&g_P[((size_t)t * HID + j) * B_SZ + b0] = o;
    }
}

// ---------------- persistent recurrence kernel (r8, unchanged) ----------
// grid (32 jb, 4 bb) = 128 CTAs, 512 threads = 16 warps. All CTAs resident.
// Wh slice [1024 k][32 j] in smem for the whole kernel (128 KB).
// Sync: counting barrier (red.add.release arrive, tid0 polls w/ nanosleep).
// h slice loaded in 2 pipelined 32k chunks so chunk B's chip-BW drain hides
// under chunk A's FFMA2 phase. P[t+1] register double-buffered.
__global__ __launch_bounds__(512) void rnn_persistent_kernel(const float* __restrict__ Wh)
{
    extern __shared__ float smem[];
    float* whs    = smem;            // [1024 k][32 j]        = 32768 floats (128 KB)
    float* hstage = smem + 32768;    // [16 warp][1024]       = 16384 floats (64 KB)

    const int tid = threadIdx.x;
    const int w   = tid >> 5;
    const int l   = tid & 31;
    const int jp  = l & 15;            // j pair: j_local = jp*2 + {0,1}
    const int bh  = l >> 4;            // b half: b_local = bh*8 + {0..7}
    const int jb  = blockIdx.x;        // 32 blocks of 32 j
    const int bb  = blockIdx.y;        // 4 blocks of 16 b

    unsigned long long* const cnt = &g_cnt[bb * 16];
    const unsigned long long per_launch =
        (unsigned long long)GROUP_CTAS * (unsigned long long)ROUNDS;
    const unsigned long long base = (*cnt / per_launch) * per_launch;

    // ---- load Wh slice into smem once: whs[k*32 + jl] ----
    {
        const float4* wh4  = (const float4*)Wh;    // Wh[k][j], row = 256 f4
        float4*       whs4 = (float4*)whs;         // row = 8 f4
#pragma unroll
        for (int i = 0; i < 16; i++) {
            int idx = tid + i * 512;               // 8192 float4
            int k = idx >> 3, q = idx & 7;
            whs4[k * 8 + q] = wh4[(size_t)k * 256 + jb * 8 + q];
        }
    }
    // ---- zero h0 slice, arrive round 1 ----
    {
        int jl = tid >> 4, bl = tid & 15;
        g_h[0][(jb * 32 + jl) * B_SZ + bb * 16 + bl] = 0.f;
    }
    __syncthreads();
    if (tid == 0) red_add_release(cnt, 1ULL);

    const int k0w = w * 64;
    float* hst = hstage + w * 1024;

    const float* pptr0 = &g_P[((size_t)(jb * 32 + (tid >> 4))) * B_SZ + bb * 16 + (tid & 15)];
    float* const hn_base0 = &g_h[0][(jb * 32 + (tid >> 4)) * B_SZ + bb * 16 + (tid & 15)];
    float* const hn_base1 = &g_h[1][(jb * 32 + (tid >> 4)) * B_SZ + bb * 16 + (tid & 15)];

    // per-lane chunk staging index math: 32k x 16b chunk = 128 f4, 4 per lane
    const int c_kk[4] = { (l) >> 2, (l + 32) >> 2, (l + 64) >> 2, (l + 96) >> 2 };
    const int c_q[4]  = { (l) & 3,  (l + 32) & 3,  (l + 64) & 3,  (l + 96) & 3  };

    // P double-buffer: load P[0] up front (hidden under the round-1 wait)
    float pval = __ldcs(pptr0);

    for (int t = 0; t < T_STEPS; t++) {
        const float4* hp4 = (const float4*)g_h[t & 1];   // h[k][b], row = 16 f4

        // ---- wait for round t+1 (everyone published h_t) ----
        if (tid == 0) {
            const unsigned long long need =
                base + (unsigned long long)GROUP_CTAS * (unsigned long long)(t + 1);
            while (ld_acquire(cnt) < need) { __nanosleep(64); }
        }
        __syncthreads();

        // ---- chunk A load (k0w .. k0w+32) ----
        float4 ha[4];
#pragma unroll
        for (int i = 0; i < 4; i++)
            ha[i] = ldcg4(&hp4[(size_t)(k0w + c_kk[i]) * 16 + bb * 4 + c_q[i]]);
#pragma unroll
        for (int i = 0; i < 4; i++)
            *(float4*)&hst[c_kk[i] * 16 + c_q[i] * 4] = ha[i];
        __syncwarp();

        // ---- chunk B load issued (k0w+32 .. k0w+64), drains under compute A ----
        float4 hb[4];
#pragma unroll
        for (int i = 0; i < 4; i++)
            hb[i] = ldcg4(&hp4[(size_t)(k0w + 32 + c_kk[i]) * 16 + bb * 4 + c_q[i]]);

        // prefetch P for next step (register-carried across the barrier)
        float pnext = 0.f;
        if (t + 1 < T_STEPS)
            pnext = __ldcs(pptr0 + (size_t)(t + 1) * (HID * B_SZ));

        unsigned long long acc[2][4];
#pragma unroll
        for (int jj = 0; jj < 2; jj++)
#pragma unroll
            for (int p = 0; p < 4; p++) acc[jj][p] = 0ull;

        const float* wrow = whs + (size_t)k0w * 32;

        // ---- compute chunk A ----
#pragma unroll
        for (int kk = 0; kk < 32; kk++) {
            ulonglong2 hv01 = *(const ulonglong2*)&hst[kk * 16 + bh * 8];
            ulonglong2 hv23 = *(const ulonglong2*)&hst[kk * 16 + bh * 8 + 4];
            float2 wp = *(const float2*)&wrow[kk * 32 + jp * 2];
            unsigned long long w0 = pack2(wp.x, wp.x);
            unsigned long long w1 = pack2(wp.y, wp.y);
            ffma2(acc[0][0], hv01.x, w0);
            ffma2(acc[0][1], hv01.y, w0);
            ffma2(acc[0][2], hv23.x, w0);
            ffma2(acc[0][3], hv23.y, w0);
            ffma2(acc[1][0], hv01.x, w1);
            ffma2(acc[1][1], hv01.y, w1);
            ffma2(acc[1][2], hv23.x, w1);
            ffma2(acc[1][3], hv23.y, w1);
        }

        // ---- stage chunk B, compute it ----
#pragma unroll
        for (int i = 0; i < 4; i++)
            *(float4*)&hst[(32 + c_kk[i]) * 16 + c_q[i] * 4] = hb[i];
        __syncwarp();

#pragma unroll
        for (int kk = 32; kk < 64; kk++) {
            ulonglong2 hv01 = *(const ulonglong2*)&hst[kk * 16 + bh * 8];
            ulonglong2 hv23 = *(const ulonglong2*)&hst[kk * 16 + bh * 8 + 4];
            float2 wp = *(const float2*)&wrow[kk * 32 + jp * 2];
            unsigned long long w0 = pack2(wp.x, wp.x);
            unsigned long long w1 = pack2(wp.y, wp.y);
            ffma2(acc[0][0], hv01.x, w0);
            ffma2(acc[0][1], hv01.y, w0);
            ffma2(acc[0][2], hv23.x, w0);
            ffma2(acc[0][3], hv23.y, w0);
            ffma2(acc[1][0], hv01.x, w1);
            ffma2(acc[1][1], hv01.y, w1);
            ffma2(acc[1][2], hv23.x, w1);
            ffma2(acc[1][3], hv23.y, w1);
        }

        // write k-partials into own warp region
#pragma unroll
        for (int jj = 0; jj < 2; jj++) {
            int o = (jp * 2 + jj) * 16 + bh * 8;
            float2 a0 = unpack2(acc[jj][0]), a1 = unpack2(acc[jj][1]);
            float2 a2 = unpack2(acc[jj][2]), a3 = unpack2(acc[jj][3]);
            *(float4*)&hst[o]     = make_float4(a0.x, a0.y, a1.x, a1.y);
            *(float4*)&hst[o + 4] = make_float4(a2.x, a2.y, a3.x, a3.y);
        }
        __syncthreads();

        // each thread finalizes one output o = tid, stores h_{t+1}
        {
            float s = 0.f;
#pragma unroll
            for (int ww = 0; ww < 16; ww++) s += hstage[ww * 1024 + tid];
            float* hn = ((t + 1) & 1) ? hn_base1 : hn_base0;
            *hn = tanhf(pval + s);
        }
        __syncthreads();
        if (tid == 0) red_add_release(cnt, 1ULL);   // arrive round t+2

        pval = pnext;
    }
}

// ---------------- final: y[b][o] = sum_j h[j][b]*W2[j][o] + b2[o] ----------------
__global__ __launch_bounds__(128) void final_kernel(
    const float* __restrict__ W2, const float* __restrict__ b2,
    float* __restrict__ out)
{
    __shared__ __align__(16) float hs[128 * 16];
    __shared__ __align__(16) float ws[128 * 32];

    const int tid = threadIdx.x;
    const int ol = tid & 31;
    const int bt = tid >> 5;
    const int ob = blockIdx.x;
    const int bb = blockIdx.y;

    const float* hfin = g_h[T_STEPS & 1];
    const float4* hp4 = (const float4*)hfin;
    const float4* w24 = (const float4*)W2;

    unsigned long long acc0 = 0ull, acc1 = 0ull;

    for (int c = 0; c < 8; c++) {
        const int k0 = c * 128;
#pragma unroll
        for (int i = 0; i < 4; i++) {
            int idx = tid + i * 128; int row = idx >> 2, q = idx & 3;
            *(float4*)&hs[row * 16 + q * 4] = hp4[(size_t)(k0 + row) * 16 + bb * 4 + q];
        }
#pragma unroll
        for (int i = 0; i < 8; i++) {
            int idx = tid + i * 128; int row = idx >> 3, q = idx & 7;
            *(float4*)&ws[row * 32 + q * 4] = w24[(size_t)(k0 + row) * 64 + ob * 8 + q];
        }
        __syncthreads();
#pragma unroll 8
        for (int kk = 0; kk < 128; kk++) {
            ulonglong2 hv = *(const ulonglong2*)&hs[kk * 16 + bt * 4];
            float w = ws[kk * 32 + ol];
            unsigned long long wp = pack2(w, w);
            ffma2(acc0, hv.x, wp);
            ffma2(acc1, hv.y, wp);
        }
        __syncthreads();
    }

    const int o = ob * 32 + ol;
    const int b0 = bb * 16 + bt * 4;
    const float bo = b2[o];
    float2 a0 = unpack2(acc0), a1 = unpack2(acc1);
    out[(b0 + 0) * OUT_SZ + o] = a0.x + bo;
    out[(b0 + 1) * OUT_SZ + o] = a0.y + bo;
    out[(b0 + 2) * OUT_SZ + o] = a1.x + bo;
    out[(b0 + 3) * OUT_SZ + o] = a1.y + bo;
}

// ---------------- launch ----------------
extern "C" void kernel_launch(void* const* d_in, const int* in_sizes, int n_in,
                              void* d_out, int out_size)
{
    const float* x   = (const float*)d_in[0];
    const float* Wx  = (const float*)d_in[1];
    const float* Wh  = (const float*)d_in[2];
    const float* b   = (const float*)d_in[3];
    const float* W2  = (const float*)d_in[4];
    const float* b2  = (const float*)d_in[5];
    float* out = (float*)d_out;

    const int SMEM_BYTES = (32768 + 16384) * 4;   // 192 KB dynamic smem
    static bool attr_done = false;
    if (!attr_done) {
        cudaFuncSetAttribute(rnn_persistent_kernel,
                             cudaFuncAttributeMaxDynamicSharedMemorySize, SMEM_BYTES);
        attr_done = true;
    }

    precompute_kernel<<<dim3(16, T_STEPS), 256>>>(x, Wx, b);
    rnn_persistent_kernel<<<dim3(32, 4), 512, SMEM_BYTES>>>(Wh);
    final_kernel<<<dim3(8, 4), 128>>>(W2, b2, out);
}

// round 16
// speedup vs baseline: 1.3295x; 1.0083x over previous
#include <cuda_runtime.h>
#include <cuda_bf16.h>
#include <cstdint>

// Problem constants
#define T_TOTAL 512
#define T_STEPS 511     // reference output uses H[-2] = h after step index 510
#define B_SZ    64
#define D_IN    256
#define HID     1024
#define OUT_SZ  256
#define GROUP_CTAS 32   // CTAs per bb exchange group
#define ROUNDS   512    // 1 init + 511 steps -> arrivals per CTA per launch

// Scratch (static __device__ — no allocations allowed)
__device__ float g_P[(size_t)T_STEPS * HID * B_SZ];   // [t][j][b]  ~134 MB
__device__ float g_h[2][HID * B_SZ];                  // [j][b] double buffer

// one counting-barrier line per bb group (zero-init; monotone: each launch
// adds exactly GROUP_CTAS*ROUNDS, so base = floor(cnt / (32*512)) * (32*512)
// is launch-invariant even if CTAs read it at slightly different times).
__device__ __align__(128) unsigned long long g_cnt[4 * 16];

// ---------------- f32x2 packed-FMA helpers (sm_103a FFMA2) ----------------
__device__ __forceinline__ unsigned long long pack2(float a, float b) {
    unsigned long long r;
    asm("mov.b64 %0, {%1, %2};" : "=l"(r) : "f"(a), "f"(b));
    return r;
}
__device__ __forceinline__ float2 unpack2(unsigned long long v) {
    float2 r;
    asm("mov.b64 {%0, %1}, %2;" : "=f"(r.x), "=f"(r.y) : "l"(v));
    return r;
}
__device__ __forceinline__ void ffma2(unsigned long long& acc,
                                      unsigned long long a,
                                      unsigned long long b) {
    asm("fma.rn.f32x2 %0, %1, %2, %0;" : "+l"(acc) : "l"(a), "l"(b));
}
// hardware tanh (MUFU.TANH, sm_75+): 1 instruction vs ~15-20 for tanhf.
// max err ~1e-5 abs, contracting recurrence -> well under the 1e-3 gate.
__device__ __forceinline__ float tanh_approx(float x) {
    float r;
    asm("tanh.approx.f32 %0, %1;" : "=f"(r) : "f"(x));
    return r;
}
// L1-bypassing vector load (cross-SM coherent at L2) for the h ring buffer
__device__ __forceinline__ float4 ldcg4(const float4* p) {
    float4 v;
    asm volatile("ld.global.cg.v4.f32 {%0,%1,%2,%3}, [%4];"
                 : "=f"(v.x), "=f"(v.y), "=f"(v.z), "=f"(v.w) : "l"(p));
    return v;
}
__device__ __forceinline__ unsigned long long ld_acquire(const unsigned long long* p) {
    unsigned long long v;
    asm volatile("ld.acquire.gpu.global.u64 %0, [%1];" : "=l"(v) : "l"(p) : "memory");
    return v;
}
__device__ __forceinline__ void red_add_release(unsigned long long* p,
                                                unsigned long long v) {
    asm volatile("red.release.gpu.global.add.u64 [%0], %1;"
                 :: "l"(p), "l"(v) : "memory");
}

// ---------------- precompute: P[t][j][b] = sum_d x[t][b][d]*Wx[d][j] + bias[j] --------
// r14 version (best measured: 494us, passed). x staged at ODD row stride 65
// (inner-loop x reads ~2-way conflicts); ws explicitly 16B-aligned.
__global__ __launch_bounds__(256, 4) void precompute_kernel(
    const float* __restrict__ x, const float* __restrict__ Wx,
    const float* __restrict__ bias)
{
    __shared__ __align__(16) float xs0[64 * 65 + 4];  // [b][d]  ODD stride 65
    __shared__ __align__(16) float ws[64 * 64];       // [d][j]  float4-accessed

    const int t  = blockIdx.y;
    const int jb = blockIdx.x;
    const int tid = threadIdx.x;
    const int jt = tid & 15;
    const int bt = tid >> 4;

    const float4* x4  = (const float4*)x;
    const float4* Wx4 = (const float4*)Wx;

    unsigned long long acc[4][2];
#pragma unroll
    for (int jj = 0; jj < 4; jj++) { acc[jj][0] = 0ull; acc[jj][1] = 0ull; }

    for (int dt = 0; dt < 4; dt++) {
        // stage x tile: natural [b][d], odd stride, scalar stores
#pragma unroll
        for (int i = 0; i < 4; i++) {
            int idx = tid + i * 256;
            int b = idx >> 4, q = idx & 15;
            float4 v = x4[(size_t)t * 4096 + b * 64 + dt * 16 + q];
            float* dst = &xs0[b * 65 + q * 4];
            dst[0] = v.x; dst[1] = v.y; dst[2] = v.z; dst[3] = v.w;
        }
        // stage Wx tile : ws[d][j] (float4, conflict-free, 16B-aligned)
#pragma unroll
        for (int i = 0; i < 4; i++) {
            int idx = tid + i * 256;
            int row = idx >> 4, q = idx & 15;
            *(float4*)&ws[row * 64 + q * 4] =
                Wx4[(size_t)(dt * 64 + row) * 256 + jb * 16 + q];
        }
        __syncthreads();

        const float* xr = &xs0[bt * 4 * 65];
#pragma unroll 8
        for (int dd = 0; dd < 64; dd++) {
            unsigned long long xv0 = pack2(xr[dd], xr[dd + 65]);
            unsigned long long xv1 = pack2(xr[dd + 130], xr[dd + 195]);
            float4 wv = *(const float4*)&ws[dd * 64 + jt * 4];
            unsigned long long w0 = pack2(wv.x, wv.x);
            unsigned long long w1 = pack2(wv.y, wv.y);
            unsigned long long w2 = pack2(wv.z, wv.z);
            unsigned long long w3 = pack2(wv.w, wv.w);
            ffma2(acc[0][0], xv0, w0); ffma2(acc[0][1], xv1, w0);
            ffma2(acc[1][0], xv0, w1); ffma2(acc[1][1], xv1, w1);
            ffma2(acc[2][0], xv0, w2); ffma2(acc[2][1], xv1, w2);
            ffma2(acc[3][0], xv0, w3); ffma2(acc[3][1], xv1, w3);
        }
        __syncthreads();
    }

    const int b0 = bt * 4;
#pragma unroll
    for (int jj = 0; jj < 4; jj++) {
        int j = jb * 64 + jt * 4 + jj;
        float bj = bias[j];
        float2 a0 = unpack2(acc[jj][0]);
        float2 a1 = unpack2(acc[jj][1]);
        float4 o = make_float4(a0.x + bj, a0.y + bj, a1.x + bj, a1.y + bj);
        *(float4*)&g_P[((size_t)t * HID + j) * B_SZ + b0] = o;
    }
}

// ---------------- persistent recurrence kernel (r8 + MUFU tanh + tighter poll) ----
// grid (32 jb, 4 bb) = 128 CTAs, 512 threads = 16 warps. All CTAs resident.
// Wh slice [1024 k][32 j] in smem for the whole kernel (128 KB).
// Sync: counting barrier (red.add.release arrive, tid0 polls w/ nanosleep 32).
// h slice loaded in 2 pipelined 32k chunks so chunk B's chip-BW drain hides
// under chunk A's FFMA2 phase. P[t+1] register double-buffered.
__global__ __launch_bounds__(512) void rnn_persistent_kernel(const float* __restrict__ Wh)
{
    extern __shared__ float smem[];
    float* whs    = smem;            // [1024 k][32 j]        = 32768 floats (128 KB)
    float* hstage = smem + 32768;    // [16 warp][1024]       = 16384 floats (64 KB)

    const int tid = threadIdx.x;
    const int w   = tid >> 5;
    const int l   = tid & 31;
    const int jp  = l & 15;            // j pair: j_local = jp*2 + {0,1}
    const int bh  = l >> 4;            // b half: b_local = bh*8 + {0..7}
    const int jb  = blockIdx.x;        // 32 blocks of 32 j
    const int bb  = blockIdx.y;        // 4 blocks of 16 b

    unsigned long long* const cnt = &g_cnt[bb * 16];
    const unsigned long long per_launch =
        (unsigned long long)GROUP_CTAS * (unsigned long long)ROUNDS;
    const unsigned long long base = (*cnt / per_launch) * per_launch;

    // ---- load Wh slice into smem once: whs[k*32 + jl] ----
    {
        const float4* wh4  = (const float4*)Wh;    // Wh[k][j], row = 256 f4
        float4*       whs4 = (float4*)whs;         // row = 8 f4
#pragma unroll
        for (int i = 0; i < 16; i++) {
            int idx = tid + i * 512;               // 8192 float4
            int k = idx >> 3, q = idx & 7;
            whs4[k * 8 + q] = wh4[(size_t)k * 256 + jb * 8 + q];
        }
    }
    // ---- zero h0 slice, arrive round 1 ----
    {
        int jl = tid >> 4, bl = tid & 15;
        g_h[0][(jb * 32 + jl) * B_SZ + bb * 16 + bl] = 0.f;
    }
    __syncthreads();
    if (tid == 0) red_add_release(cnt, 1ULL);

    const int k0w = w * 64;
    float* hst = hstage + w * 1024;

    const float* pptr0 = &g_P[((size_t)(jb * 32 + (tid >> 4))) * B_SZ + bb * 16 + (tid & 15)];
    float* const hn_base0 = &g_h[0][(jb * 32 + (tid >> 4)) * B_SZ + bb * 16 + (tid & 15)];
    float* const hn_base1 = &g_h[1][(jb * 32 + (tid >> 4)) * B_SZ + bb * 16 + (tid & 15)];

    // per-lane chunk staging index math: 32k x 16b chunk = 128 f4, 4 per lane
    const int c_kk[4] = { (l) >> 2, (l + 32) >> 2, (l + 64) >> 2, (l + 96) >> 2 };
    const int c_q[4]  = { (l) & 3,  (l + 32) & 3,  (l + 64) & 3,  (l + 96) & 3  };

    // P double-buffer: load P[0] up front (hidden under the round-1 wait)
    float pval = __ldcs(pptr0);

    for (int t = 0; t < T_STEPS; t++) {
        const float4* hp4 = (const float4*)g_h[t & 1];   // h[k][b], row = 16 f4

        // ---- wait for round t+1 (everyone published h_t) ----
        if (tid == 0) {
            const unsigned long long need =
                base + (unsigned long long)GROUP_CTAS * (unsigned long long)(t + 1);
            while (ld_acquire(cnt) < need) { __nanosleep(32); }
        }
        __syncthreads();

        // ---- chunk A load (k0w .. k0w+32) ----
        float4 ha[4];
#pragma unroll
        for (int i = 0; i < 4; i++)
            ha[i] = ldcg4(&hp4[(size_t)(k0w + c_kk[i]) * 16 + bb * 4 + c_q[i]]);
#pragma unroll
        for (int i = 0; i < 4; i++)
            *(float4*)&hst[c_kk[i] * 16 + c_q[i] * 4] = ha[i];
        __syncwarp();

        // ---- chunk B load issued (k0w+32 .. k0w+64), drains under compute A ----
        float4 hb[4];
#pragma unroll
        for (int i = 0; i < 4; i++)
            hb[i] = ldcg4(&hp4[(size_t)(k0w + 32 + c_kk[i]) * 16 + bb * 4 + c_q[i]]);

        // prefetch P for next step (register-carried across the barrier)
        float pnext = 0.f;
        if (t + 1 < T_STEPS)
            pnext = __ldcs(pptr0 + (size_t)(t + 1) * (HID * B_SZ));

        unsigned long long acc[2][4];
#pragma unroll
        for (int jj = 0; jj < 2; jj++)
#pragma unroll
            for (int p = 0; p < 4; p++) acc[jj][p] = 0ull;

        const float* wrow = whs + (size_t)k0w * 32;

        // ---- compute chunk A ----
#pragma unroll
        for (int kk = 0; kk < 32; kk++) {
            ulonglong2 hv01 = *(const ulonglong2*)&hst[kk * 16 + bh * 8];
            ulonglong2 hv23 = *(const ulonglong2*)&hst[kk * 16 + bh * 8 + 4];
            float2 wp = *(const float2*)&wrow[kk * 32 + jp * 2];
            unsigned long long w0 = pack2(wp.x, wp.x);
            unsigned long long w1 = pack2(wp.y, wp.y);
            ffma2(acc[0][0], hv01.x, w0);
            ffma2(acc[0][1], hv01.y, w0);
            ffma2(acc[0][2], hv23.x, w0);
            ffma2(acc[0][3], hv23.y, w0);
            ffma2(acc[1][0], hv01.x, w1);
            ffma2(acc[1][1], hv01.y, w1);
            ffma2(acc[1][2], hv23.x, w1);
            ffma2(acc[1][3], hv23.y, w1);
        }

        // ---- stage chunk B, compute it ----
#pragma unroll
        for (int i = 0; i < 4; i++)
            *(float4*)&hst[(32 + c_kk[i]) * 16 + c_q[i] * 4] = hb[i];
        __syncwarp();

#pragma unroll
        for (int kk = 32; kk < 64; kk++) {
            ulonglong2 hv01 = *(const ulonglong2*)&hst[kk * 16 + bh * 8];
            ulonglong2 hv23 = *(const ulonglong2*)&hst[kk * 16 + bh * 8 + 4];
            float2 wp = *(const float2*)&wrow[kk * 32 + jp * 2];
            unsigned long long w0 = pack2(wp.x, wp.x);
            unsigned long long w1 = pack2(wp.y, wp.y);
            ffma2(acc[0][0], hv01.x, w0);
            ffma2(acc[0][1], hv01.y, w0);
            ffma2(acc[0][2], hv23.x, w0);
            ffma2(acc[0][3], hv23.y, w0);
            ffma2(acc[1][0], hv01.x, w1);
            ffma2(acc[1][1], hv01.y, w1);
            ffma2(acc[1][2], hv23.x, w1);
            ffma2(acc[1][3], hv23.y, w1);
        }

        // write k-partials into own warp region
#pragma unroll
        for (int jj = 0; jj < 2; jj++) {
            int o = (jp * 2 + jj) * 16 + bh * 8;
            float2 a0 = unpack2(acc[jj][0]), a1 = unpack2(acc[jj][1]);
            float2 a2 = unpack2(acc[jj][2]), a3 = unpack2(acc[jj][3]);
            *(float4*)&hst[o]     = make_float4(a0.x, a0.y, a1.x, a1.y);
            *(float4*)&hst[o + 4] = make_float4(a2.x, a2.y, a3.x, a3.y);
        }
        __syncthreads();

        // each thread finalizes one output o = tid, stores h_{t+1}
        {
            float s = 0.f;
#pragma unroll
            for (int ww = 0; ww < 16; ww++) s += hstage[ww * 1024 + tid];
            float* hn = ((t + 1) & 1) ? hn_base1 : hn_base0;
            *hn = tanh_approx(pval + s);
        }
        __syncthreads();
        if (tid == 0) red_add_release(cnt, 1ULL);   // arrive round t+2

        pval = pnext;
    }
}

// ---------------- final: y[b][o] = sum_j h[j][b]*W2[j][o] + b2[o] ----------------
__global__ __launch_bounds__(128) void final_kernel(
    const float* __restrict__ W2, const float* __restrict__ b2,
    float* __restrict__ out)
{
    __shared__ __align__(16) float hs[128 * 16];
    __shared__ __align__(16) float ws[128 * 32];

    const int tid = threadIdx.x;
    const int ol = tid & 31;
    const int bt = tid >> 5;
    const int ob = blockIdx.x;
    const int bb = blockIdx.y;

    const float* hfin = g_h[T_STEPS & 1];
    const float4* hp4 = (const float4*)hfin;
    const float4* w24 = (const float4*)W2;

    unsigned long long acc0 = 0ull, acc1 = 0ull;

    for (int c = 0; c < 8; c++) {
        const int k0 = c * 128;
#pragma unroll
        for (int i = 0; i < 4; i++) {
            int idx = tid + i * 128; int row = idx >> 2, q = idx & 3;
            *(float4*)&hs[row * 16 + q * 4] = hp4[(size_t)(k0 + row) * 16 + bb * 4 + q];
        }
#pragma unroll
        for (int i = 0; i < 8; i++) {
            int idx = tid + i * 128; int row = idx >> 3, q = idx & 7;
            *(float4*)&ws[row * 32 + q * 4] = w24[(size_t)(k0 + row) * 64 + ob * 8 + q];
        }
        __syncthreads();
#pragma unroll 8
        for (int kk = 0; kk < 128; kk++) {
            ulonglong2 hv = *(const ulonglong2*)&hs[kk * 16 + bt * 4];
            float w = ws[kk * 32 + ol];
            unsigned long long wp = pack2(w, w);
            ffma2(acc0, hv.x, wp);
            ffma2(acc1, hv.y, wp);
        }
        __syncthreads();
    }

    const int o = ob * 32 + ol;
    const int b0 = bb * 16 + bt * 4;
    const float bo = b2[o];
    float2 a0 = unpack2(acc0), a1 = unpack2(acc1);
    out[(b0 + 0) * OUT_SZ + o] = a0.x + bo;
    out[(b0 + 1) * OUT_SZ + o] = a0.y + bo;
    out[(b0 + 2) * OUT_SZ + o] = a1.x + bo;
    out[(b0 + 3) * OUT_SZ + o] = a1.y + bo;
}

// ---------------- launch ----------------
extern "C" void kernel_launch(void* const* d_in, const int* in_sizes, int n_in,
                              void* d_out, int out_size)
{
    const float* x   = (const float*)d_in[0];
    const float* Wx  = (const float*)d_in[1];
    const float* Wh  = (const float*)d_in[2];
    const float* b   = (const float*)d_in[3];
    const float* W2  = (const float*)d_in[4];
    const float* b2  = (const float*)d_in[5];
    float* out = (float*)d_out;

    const int SMEM_BYTES = (32768 + 16384) * 4;   // 192 KB dynamic smem
    static bool attr_done = false;
    if (!attr_done) {
        cudaFuncSetAttribute(rnn_persistent_kernel,
                             cudaFuncAttributeMaxDynamicSharedMemorySize, SMEM_BYTES);
        attr_done = true;
    }

    precompute_kernel<<<dim3(16, T_STEPS), 256>>>(x, Wx, b);
    rnn_persistent_kernel<<<dim3(32, 4), 512, SMEM_BYTES>>>(Wh);
    final_kernel<<<dim3(8, 4), 128>>>(W2, b2, out);
}